// round 10
// baseline (speedup 1.0000x reference)
#include <cuda_runtime.h>
#include <math.h>

#define BATCH   16
#define D_IN    1024
#define T_IN    4096
#define CB_SIZE 8192
#define CB_DIM  512
#define T1      2048
#define T2      1024
#define NTOK    (BATCH * T2)
#define NSPLIT  8
#define NTILES  8
#define NSLOT   (NSPLIT * NTILES)

// Scratch — referenced only from device code.
__device__ float g_y1 [BATCH * CB_DIM * T1];   // 64 MB conv1 out [b][co][t]
__device__ float g_y2 [BATCH * CB_DIM * T2];   // 32 MB conv2 out [b][co][t]
__device__ float g_cbT[CB_DIM * CB_SIZE];      // 16 MB normalized codebook [d][code]
__device__ float g_inorm[CB_SIZE];
__device__ float g_pv[(size_t)NTOK * NSLOT];
__device__ int   g_pi[(size_t)NTOK * NSLOT];

// ---------------- codebook inverse norms ----------------
__global__ void __launch_bounds__(128) norm_kernel(const float* __restrict__ cb) {
    __shared__ float red[4];
    int row = blockIdx.x;
    const float* r = cb + (size_t)row * CB_DIM;
    float s = 0.f;
    for (int i = threadIdx.x; i < CB_DIM; i += 128) { float v = r[i]; s += v * v; }
    #pragma unroll
    for (int o = 16; o; o >>= 1) s += __shfl_down_sync(0xffffffffu, s, o);
    if ((threadIdx.x & 31) == 0) red[threadIdx.x >> 5] = s;
    __syncthreads();
    if (threadIdx.x == 0) {
        float t = red[0] + red[1] + red[2] + red[3];
        g_inorm[row] = 1.f / fmaxf(sqrtf(t), 1e-12f);
    }
}

// ---------------- normalize + transpose codebook -> g_cbT[d][code] ----------------
__global__ void __launch_bounds__(256) transpose_norm_kernel(const float* __restrict__ cb) {
    __shared__ float tile[32][33];
    int r0 = blockIdx.x * 32;
    int d0 = blockIdx.y * 32;
    int tx = threadIdx.x;
    int ty = threadIdx.y;
    #pragma unroll
    for (int i = ty; i < 32; i += 8)
        tile[i][tx] = cb[(size_t)(r0 + i) * CB_DIM + d0 + tx] * g_inorm[r0 + i];
    __syncthreads();
    #pragma unroll
    for (int i = ty; i < 32; i += 8)
        g_cbT[(size_t)(d0 + i) * CB_SIZE + r0 + tx] = tile[tx][i];
}

// ---------------- stride-2 conv1d (k=3, pad=1), 128x128 tile, 8x8 micro ----------------
// Phase-split X smem: Xe[p]=x[2(t0+p)], Xo[q]=x[2(t0+q)-1].
// Inner loop indexes xe/xo fragments DIRECTLY per k (no staging copies -> no spill):
//   k=0 -> xo[j], k=1 -> xe[j], k=2 -> xo[j+1]
template <int CIN, int TIN, int STAGE>
__global__ void __launch_bounds__(256, 2) conv_s2_kernel(const float* __restrict__ xin,
                                                         const float* __restrict__ W) {
    constexpr int TOUT = TIN / 2;
    const float* X = (STAGE == 0) ? xin : (const float*)g_y1;
    float*       Y = (STAGE == 0) ? g_y1 : g_y2;

    __shared__ float Wt[24][132];   // [ci*3+k][co]
    __shared__ float Xe[8][128];    // even phase
    __shared__ float Xo[8][132];    // odd phase, 129 used

    int t0  = blockIdx.x * 128;
    int co0 = blockIdx.y * 128;
    int b   = blockIdx.z;
    int tid = threadIdx.x;
    int tx  = tid & 15;    // t dir
    int ty  = tid >> 4;    // co dir

    float acc[8][8];
    #pragma unroll
    for (int i = 0; i < 8; i++)
        #pragma unroll
        for (int j = 0; j < 8; j++) acc[i][j] = 0.f;

    const float* Xb = X + (size_t)b * CIN * TIN;

    for (int c0 = 0; c0 < CIN; c0 += 8) {
        // ---- weights: 128 co x 24 -> transposed smem
        #pragma unroll
        for (int s = 0; s < 3; s++) {
            int f  = tid + s * 256;
            int co = f / 6, q = f % 6;
            float4 w4 = *(const float4*)(W + (size_t)(co0 + co) * (CIN * 3) + c0 * 3 + q * 4);
            Wt[q * 4 + 0][co] = w4.x;
            Wt[q * 4 + 1][co] = w4.y;
            Wt[q * 4 + 2][co] = w4.z;
            Wt[q * 4 + 3][co] = w4.w;
        }
        // ---- x: float4 loads, even/odd scatter
        #pragma unroll
        for (int s = 0; s < 2; s++) {
            int f  = tid + s * 256;
            int ci = f >> 6, u = f & 63;
            float4 x4 = *(const float4*)(Xb + (size_t)(c0 + ci) * TIN + 2 * t0 + u * 4);
            Xe[ci][2 * u]     = x4.x;
            Xo[ci][2 * u + 1] = x4.y;
            Xe[ci][2 * u + 1] = x4.z;
            Xo[ci][2 * u + 2] = x4.w;
        }
        if (tid < 8) {
            float v = 0.f;
            if (t0 > 0) v = Xb[(size_t)(c0 + tid) * TIN + 2 * t0 - 1];
            Xo[tid][0] = v;
        }
        __syncthreads();

        #pragma unroll
        for (int ci = 0; ci < 8; ci++) {
            float xe[8], xo[9];
            *(float4*)&xe[0] = *(const float4*)&Xe[ci][tx * 8];
            *(float4*)&xe[4] = *(const float4*)&Xe[ci][tx * 8 + 4];
            *(float4*)&xo[0] = *(const float4*)&Xo[ci][tx * 8];
            *(float4*)&xo[4] = *(const float4*)&Xo[ci][tx * 8 + 4];
            xo[8] = Xo[ci][tx * 8 + 8];
            #pragma unroll
            for (int k = 0; k < 3; k++) {
                float av[8];
                *(float4*)&av[0] = *(const float4*)&Wt[ci * 3 + k][ty * 8];
                *(float4*)&av[4] = *(const float4*)&Wt[ci * 3 + k][ty * 8 + 4];
                #pragma unroll
                for (int i = 0; i < 8; i++)
                    #pragma unroll
                    for (int j = 0; j < 8; j++) {
                        float xv = (k == 0) ? xo[j] : (k == 1) ? xe[j] : xo[j + 1];
                        acc[i][j] = fmaf(av[i], xv, acc[i][j]);
                    }
            }
        }
        __syncthreads();
    }

    #pragma unroll
    for (int i = 0; i < 8; i++) {
        float* yr = Y + ((size_t)b * 512 + co0 + ty * 8 + i) * TOUT + t0 + tx * 8;
        *(float4*)yr       = make_float4(acc[i][0], acc[i][1], acc[i][2], acc[i][3]);
        *(float4*)(yr + 4) = make_float4(acc[i][4], acc[i][5], acc[i][6], acc[i][7]);
    }
}

// ---------------- scoring GEMM: 128 tok x 128 codes, 8x8 micro, fused argmax ----------------
__global__ void __launch_bounds__(256, 2) score_kernel() {
    __shared__ float Es[2][8][128];
    __shared__ float Cs[2][8][128];

    int split = blockIdx.x;
    int ttile = blockIdx.y;
    int b  = ttile >> 3;
    int t0 = (ttile & 7) * 128;
    int tid = threadIdx.x;
    int ty  = tid >> 4;
    int tx  = tid & 15;
    int lkk = tid >> 5;
    int lm  = tid & 31;

    const float* Ybase = g_y2 + (size_t)b * CB_DIM * T2 + t0;

    for (int nt = 0; nt < NTILES; nt++) {
        int n0 = split * (NTILES * 128) + nt * 128;

        float acc[8][8];
        #pragma unroll
        for (int i = 0; i < 8; i++)
            #pragma unroll
            for (int j = 0; j < 8; j++) acc[i][j] = 0.f;

        *(float4*)&Es[0][lkk][lm * 4] =
            *(const float4*)(Ybase + (size_t)lkk * T2 + lm * 4);
        *(float4*)&Cs[0][lkk][lm * 4] =
            *(const float4*)(g_cbT + (size_t)lkk * CB_SIZE + n0 + lm * 4);
        __syncthreads();

        int buf = 0;
        for (int k0 = 0; k0 < CB_DIM; k0 += 8) {
            if (k0 + 8 < CB_DIM) {
                *(float4*)&Es[buf ^ 1][lkk][lm * 4] =
                    *(const float4*)(Ybase + (size_t)(k0 + 8 + lkk) * T2 + lm * 4);
                *(float4*)&Cs[buf ^ 1][lkk][lm * 4] =
                    *(const float4*)(g_cbT + (size_t)(k0 + 8 + lkk) * CB_SIZE + n0 + lm * 4);
            }
            #pragma unroll
            for (int kk = 0; kk < 8; kk++) {
                float4 a0 = *(const float4*)&Es[buf][kk][ty * 8];
                float4 a1 = *(const float4*)&Es[buf][kk][ty * 8 + 4];
                float4 b0 = *(const float4*)&Cs[buf][kk][tx * 8];
                float4 b1 = *(const float4*)&Cs[buf][kk][tx * 8 + 4];
                float av[8] = {a0.x, a0.y, a0.z, a0.w, a1.x, a1.y, a1.z, a1.w};
                float bv[8] = {b0.x, b0.y, b0.z, b0.w, b1.x, b1.y, b1.z, b1.w};
                #pragma unroll
                for (int i = 0; i < 8; i++)
                    #pragma unroll
                    for (int j = 0; j < 8; j++)
                        acc[i][j] = fmaf(av[i], bv[j], acc[i][j]);
            }
            __syncthreads();
            buf ^= 1;
        }

        #pragma unroll
        for (int i = 0; i < 8; i++) {
            float bvv = -3.4e38f; int bii = 0x7fffffff;
            #pragma unroll
            for (int j = 0; j < 8; j++) {
                int n = n0 + tx * 8 + j;
                float v = acc[i][j];
                if (v > bvv) { bvv = v; bii = n; }
            }
            #pragma unroll
            for (int off = 8; off > 0; off >>= 1) {
                float ov = __shfl_xor_sync(0xffffffffu, bvv, off);
                int   oi = __shfl_xor_sync(0xffffffffu, bii, off);
                if (ov > bvv || (ov == bvv && oi < bii)) { bvv = ov; bii = oi; }
            }
            if (tx == 0) {
                int token = ttile * 128 + ty * 8 + i;
                int slot  = split * NTILES + nt;
                g_pv[(size_t)token * NSLOT + slot] = bvv;
                g_pi[(size_t)token * NSLOT + slot] = bii;
            }
        }
        __syncthreads();
    }
}

// ---------------- combine partials -> float index output ----------------
__global__ void __launch_bounds__(256) finalize_kernel(float* __restrict__ out) {
    int token = blockIdx.x * 256 + threadIdx.x;
    if (token >= NTOK) return;
    const float* pv = g_pv + (size_t)token * NSLOT;
    const int*   pi = g_pi + (size_t)token * NSLOT;
    float bv = -3.4e38f; int bi = 0x7fffffff;
    for (int s = 0; s < NSLOT; s++) {
        float v = pv[s]; int idx = pi[s];
        if (v > bv || (v == bv && idx < bi)) { bv = v; bi = idx; }
    }
    out[token] = (float)bi;
}

extern "C" void kernel_launch(void* const* d_in, const int* in_sizes, int n_in,
                              void* d_out, int out_size) {
    const float *x = 0, *w1 = 0, *w2 = 0, *cb = 0;
    for (int i = 0; i < n_in; i++) {
        switch (in_sizes[i]) {
            case BATCH * D_IN * T_IN:   x  = (const float*)d_in[i]; break;
            case CB_DIM * D_IN * 3:     w1 = (const float*)d_in[i]; break;
            case CB_DIM * CB_DIM * 3:   w2 = (const float*)d_in[i]; break;
            case CB_SIZE * CB_DIM:      cb = (const float*)d_in[i]; break;
        }
    }
    if (!x || !w1 || !w2 || !cb) {
        x  = (const float*)d_in[0];
        w1 = (const float*)d_in[1];
        w2 = (const float*)d_in[2];
        cb = (const float*)d_in[3];
    }

    norm_kernel<<<CB_SIZE, 128>>>(cb);
    transpose_norm_kernel<<<dim3(CB_SIZE / 32, CB_DIM / 32), dim3(32, 8)>>>(cb);

    conv_s2_kernel<D_IN, T_IN, 0><<<dim3(T_IN / 256, 4, BATCH), 256>>>(x, w1);
    conv_s2_kernel<CB_DIM, T1, 1><<<dim3(T1 / 256, 4, BATCH), 256>>>(nullptr, w2);

    score_kernel<<<dim3(NSPLIT, 128), 256>>>();
    finalize_kernel<<<(NTOK + 255) / 256, 256>>>((float*)d_out);
}

// round 11
// speedup vs baseline: 1.0626x; 1.0626x over previous
#include <cuda_runtime.h>
#include <math.h>

#define BATCH   16
#define D_IN    1024
#define T_IN    4096
#define CB_SIZE 8192
#define CB_DIM  512
#define T1      2048
#define T2      1024
#define NTOK    (BATCH * T2)
#define NSPLIT  8
#define NTILES  8
#define NSLOT   (NSPLIT * NTILES)

// Scratch — referenced only from device code.
__device__ float g_y1 [BATCH * CB_DIM * T1];   // 64 MB conv1 out [b][co][t]
__device__ float g_y2 [BATCH * CB_DIM * T2];   // 32 MB conv2 out [b][co][t]
__device__ float g_cbT[CB_DIM * CB_SIZE];      // 16 MB normalized codebook [d][code]
__device__ float g_inorm[CB_SIZE];
__device__ float g_pv[(size_t)NTOK * NSLOT];
__device__ int   g_pi[(size_t)NTOK * NSLOT];

// ---------------- codebook inverse norms ----------------
__global__ void __launch_bounds__(128) norm_kernel(const float* __restrict__ cb) {
    __shared__ float red[4];
    int row = blockIdx.x;
    const float* r = cb + (size_t)row * CB_DIM;
    float s = 0.f;
    for (int i = threadIdx.x; i < CB_DIM; i += 128) { float v = r[i]; s += v * v; }
    #pragma unroll
    for (int o = 16; o; o >>= 1) s += __shfl_down_sync(0xffffffffu, s, o);
    if ((threadIdx.x & 31) == 0) red[threadIdx.x >> 5] = s;
    __syncthreads();
    if (threadIdx.x == 0) {
        float t = red[0] + red[1] + red[2] + red[3];
        g_inorm[row] = 1.f / fmaxf(sqrtf(t), 1e-12f);
    }
}

// ---------------- normalize + transpose codebook -> g_cbT[d][code] ----------------
__global__ void __launch_bounds__(256) transpose_norm_kernel(const float* __restrict__ cb) {
    __shared__ float tile[32][33];
    int r0 = blockIdx.x * 32;
    int d0 = blockIdx.y * 32;
    int tx = threadIdx.x;
    int ty = threadIdx.y;
    #pragma unroll
    for (int i = ty; i < 32; i += 8)
        tile[i][tx] = cb[(size_t)(r0 + i) * CB_DIM + d0 + tx] * g_inorm[r0 + i];
    __syncthreads();
    #pragma unroll
    for (int i = ty; i < 32; i += 8)
        g_cbT[(size_t)(d0 + i) * CB_SIZE + r0 + tx] = tile[tx][i];
}

// ---------------- stride-2 conv1d (k=3, pad=1), 128x128 tile, 8x8 micro ----------------
// Phase-split X smem: Xe[p]=x[2(t0+p)], Xo[q]=x[2(t0+q)-1].
// SPLIT FRAGMENTS: thread owns t = {tx*4+j} U {64+tx*4+j}, co = {ty*4+i} U {64+ty*4+i}
// -> all float4 smem reads at 16B lane stride (conflict-free).
template <int CIN, int TIN, int STAGE>
__global__ void __launch_bounds__(256, 2) conv_s2_kernel(const float* __restrict__ xin,
                                                         const float* __restrict__ W) {
    constexpr int TOUT = TIN / 2;
    const float* X = (STAGE == 0) ? xin : (const float*)g_y1;
    float*       Y = (STAGE == 0) ? g_y1 : g_y2;

    __shared__ float Wt[24][132];   // [ci*3+k][co]
    __shared__ float Xe[8][128];    // even phase
    __shared__ float Xo[8][132];    // odd phase, 129 used

    int t0  = blockIdx.x * 128;
    int co0 = blockIdx.y * 128;
    int b   = blockIdx.z;
    int tid = threadIdx.x;
    int tx  = tid & 15;    // t dir
    int ty  = tid >> 4;    // co dir

    float acc[8][8];
    #pragma unroll
    for (int i = 0; i < 8; i++)
        #pragma unroll
        for (int j = 0; j < 8; j++) acc[i][j] = 0.f;

    const float* Xb = X + (size_t)b * CIN * TIN;

    for (int c0 = 0; c0 < CIN; c0 += 8) {
        // ---- weights: 128 co x 24 -> transposed smem
        #pragma unroll
        for (int s = 0; s < 3; s++) {
            int f  = tid + s * 256;
            int co = f / 6, q = f % 6;
            float4 w4 = *(const float4*)(W + (size_t)(co0 + co) * (CIN * 3) + c0 * 3 + q * 4);
            Wt[q * 4 + 0][co] = w4.x;
            Wt[q * 4 + 1][co] = w4.y;
            Wt[q * 4 + 2][co] = w4.z;
            Wt[q * 4 + 3][co] = w4.w;
        }
        // ---- x: float4 loads, even/odd scatter
        #pragma unroll
        for (int s = 0; s < 2; s++) {
            int f  = tid + s * 256;
            int ci = f >> 6, u = f & 63;
            float4 x4 = *(const float4*)(Xb + (size_t)(c0 + ci) * TIN + 2 * t0 + u * 4);
            Xe[ci][2 * u]     = x4.x;
            Xo[ci][2 * u + 1] = x4.y;
            Xe[ci][2 * u + 1] = x4.z;
            Xo[ci][2 * u + 2] = x4.w;
        }
        if (tid < 8) {
            float v = 0.f;
            if (t0 > 0) v = Xb[(size_t)(c0 + tid) * TIN + 2 * t0 - 1];
            Xo[tid][0] = v;
        }
        __syncthreads();

        #pragma unroll
        for (int ci = 0; ci < 8; ci++) {
            float xe[8], xoA[5], xoB[5];
            *(float4*)&xe[0]  = *(const float4*)&Xe[ci][tx * 4];
            *(float4*)&xe[4]  = *(const float4*)&Xe[ci][64 + tx * 4];
            *(float4*)&xoA[0] = *(const float4*)&Xo[ci][tx * 4];
            xoA[4] = Xo[ci][tx * 4 + 4];
            *(float4*)&xoB[0] = *(const float4*)&Xo[ci][64 + tx * 4];
            xoB[4] = Xo[ci][64 + tx * 4 + 4];
            #pragma unroll
            for (int k = 0; k < 3; k++) {
                float av[8];
                *(float4*)&av[0] = *(const float4*)&Wt[ci * 3 + k][ty * 4];
                *(float4*)&av[4] = *(const float4*)&Wt[ci * 3 + k][64 + ty * 4];
                #pragma unroll
                for (int i = 0; i < 8; i++)
                    #pragma unroll
                    for (int j = 0; j < 8; j++) {
                        float xv = (j < 4)
                            ? ((k == 0) ? xoA[j] : (k == 1) ? xe[j] : xoA[j + 1])
                            : ((k == 0) ? xoB[j - 4] : (k == 1) ? xe[j] : xoB[j - 3]);
                        acc[i][j] = fmaf(av[i], xv, acc[i][j]);
                    }
            }
        }
        __syncthreads();
    }

    #pragma unroll
    for (int i = 0; i < 8; i++) {
        int co = co0 + ((i < 4) ? (ty * 4 + i) : (64 + ty * 4 + i - 4));
        float* yr = Y + ((size_t)b * 512 + co) * TOUT + t0;
        *(float4*)(yr + tx * 4)      = make_float4(acc[i][0], acc[i][1], acc[i][2], acc[i][3]);
        *(float4*)(yr + 64 + tx * 4) = make_float4(acc[i][4], acc[i][5], acc[i][6], acc[i][7]);
    }
}

// ---------------- scoring GEMM: 128 tok x 128 codes, split-fragment 8x8 micro ----------------
__global__ void __launch_bounds__(256, 2) score_kernel() {
    __shared__ float Es[2][8][128];
    __shared__ float Cs[2][8][128];

    int split = blockIdx.x;
    int ttile = blockIdx.y;
    int b  = ttile >> 3;
    int t0 = (ttile & 7) * 128;
    int tid = threadIdx.x;
    int ty  = tid >> 4;
    int tx  = tid & 15;
    int lkk = tid >> 5;
    int lm  = tid & 31;

    const float* Ybase = g_y2 + (size_t)b * CB_DIM * T2 + t0;

    for (int nt = 0; nt < NTILES; nt++) {
        int n0 = split * (NTILES * 128) + nt * 128;

        float acc[8][8];
        #pragma unroll
        for (int i = 0; i < 8; i++)
            #pragma unroll
            for (int j = 0; j < 8; j++) acc[i][j] = 0.f;

        *(float4*)&Es[0][lkk][lm * 4] =
            *(const float4*)(Ybase + (size_t)lkk * T2 + lm * 4);
        *(float4*)&Cs[0][lkk][lm * 4] =
            *(const float4*)(g_cbT + (size_t)lkk * CB_SIZE + n0 + lm * 4);
        __syncthreads();

        int buf = 0;
        for (int k0 = 0; k0 < CB_DIM; k0 += 8) {
            if (k0 + 8 < CB_DIM) {
                *(float4*)&Es[buf ^ 1][lkk][lm * 4] =
                    *(const float4*)(Ybase + (size_t)(k0 + 8 + lkk) * T2 + lm * 4);
                *(float4*)&Cs[buf ^ 1][lkk][lm * 4] =
                    *(const float4*)(g_cbT + (size_t)(k0 + 8 + lkk) * CB_SIZE + n0 + lm * 4);
            }
            #pragma unroll
            for (int kk = 0; kk < 8; kk++) {
                float a[8], c[8];
                *(float4*)&a[0] = *(const float4*)&Es[buf][kk][ty * 4];
                *(float4*)&a[4] = *(const float4*)&Es[buf][kk][64 + ty * 4];
                *(float4*)&c[0] = *(const float4*)&Cs[buf][kk][tx * 4];
                *(float4*)&c[4] = *(const float4*)&Cs[buf][kk][64 + tx * 4];
                #pragma unroll
                for (int i = 0; i < 8; i++)
                    #pragma unroll
                    for (int j = 0; j < 8; j++)
                        acc[i][j] = fmaf(a[i], c[j], acc[i][j]);
            }
            __syncthreads();
            buf ^= 1;
        }

        #pragma unroll
        for (int i = 0; i < 8; i++) {
            float bvv = -3.4e38f; int bii = 0x7fffffff;
            #pragma unroll
            for (int j = 0; j < 8; j++) {
                // n ascending in j within thread: tx*4+0..3 then 64+tx*4+0..3
                int n = n0 + ((j < 4) ? (tx * 4 + j) : (64 + tx * 4 + j - 4));
                float v = acc[i][j];
                if (v > bvv) { bvv = v; bii = n; }
            }
            #pragma unroll
            for (int off = 8; off > 0; off >>= 1) {
                float ov = __shfl_xor_sync(0xffffffffu, bvv, off);
                int   oi = __shfl_xor_sync(0xffffffffu, bii, off);
                if (ov > bvv || (ov == bvv && oi < bii)) { bvv = ov; bii = oi; }
            }
            if (tx == 0) {
                int tok_local = (i < 4) ? (ty * 4 + i) : (64 + ty * 4 + i - 4);
                int token = ttile * 128 + tok_local;
                int slot  = split * NTILES + nt;
                g_pv[(size_t)token * NSLOT + slot] = bvv;
                g_pi[(size_t)token * NSLOT + slot] = bii;
            }
        }
        __syncthreads();
    }
}

// ---------------- combine partials -> float index output ----------------
__global__ void __launch_bounds__(256) finalize_kernel(float* __restrict__ out) {
    int token = blockIdx.x * 256 + threadIdx.x;
    if (token >= NTOK) return;
    const float* pv = g_pv + (size_t)token * NSLOT;
    const int*   pi = g_pi + (size_t)token * NSLOT;
    float bv = -3.4e38f; int bi = 0x7fffffff;
    for (int s = 0; s < NSLOT; s++) {
        float v = pv[s]; int idx = pi[s];
        if (v > bv || (v == bv && idx < bi)) { bv = v; bi = idx; }
    }
    out[token] = (float)bi;
}

extern "C" void kernel_launch(void* const* d_in, const int* in_sizes, int n_in,
                              void* d_out, int out_size) {
    const float *x = 0, *w1 = 0, *w2 = 0, *cb = 0;
    for (int i = 0; i < n_in; i++) {
        switch (in_sizes[i]) {
            case BATCH * D_IN * T_IN:   x  = (const float*)d_in[i]; break;
            case CB_DIM * D_IN * 3:     w1 = (const float*)d_in[i]; break;
            case CB_DIM * CB_DIM * 3:   w2 = (const float*)d_in[i]; break;
            case CB_SIZE * CB_DIM:      cb = (const float*)d_in[i]; break;
        }
    }
    if (!x || !w1 || !w2 || !cb) {
        x  = (const float*)d_in[0];
        w1 = (const float*)d_in[1];
        w2 = (const float*)d_in[2];
        cb = (const float*)d_in[3];
    }

    norm_kernel<<<CB_SIZE, 128>>>(cb);
    transpose_norm_kernel<<<dim3(CB_SIZE / 32, CB_DIM / 32), dim3(32, 8)>>>(cb);

    conv_s2_kernel<D_IN, T_IN, 0><<<dim3(T_IN / 256, 4, BATCH), 256>>>(x, w1);
    conv_s2_kernel<CB_DIM, T1, 1><<<dim3(T1 / 256, 4, BATCH), 256>>>(nullptr, w2);

    score_kernel<<<dim3(NSPLIT, 128), 256>>>();
    finalize_kernel<<<(NTOK + 255) / 256, 256>>>((float*)d_out);
}